// round 1
// baseline (speedup 1.0000x reference)
#include <cuda_runtime.h>

// Problem constants (static per reference)
#define NIMG 8
#define CINC 64
#define HH   112
#define WW   112
#define NP   (HH*WW)      // 12544 patches per image
#define COUTC 64
#define DD   576          // CIN*K*K, feature order d = cin*9 + kh*3 + kw (torch unfold order)
#define MEM  1025

// Scratch (device globals — no allocation allowed)
__device__ float d_S[NIMG*NP];              // per-pixel channel sums
__device__ int   d_bins[NIMG*NP];           // bin per patch
__device__ int   d_first[NIMG*MEM];         // first-occurring patch idx per bin (init NP)
__device__ float d_rep[NIMG*MEM*COUTC];     // representative outputs
__device__ float d_Wt[DD*COUTC];            // transposed weight: Wt[d*64 + c]

// K1: channel sums + init first table + weight transpose (fused init pass)
__global__ void k_prep(const float* __restrict__ fmap,
                       const float* __restrict__ weight) {
    int tid = blockIdx.x * blockDim.x + threadIdx.x;

    if (tid < NIMG*MEM) d_first[tid] = NP;

    if (tid < COUTC*DD) {
        int c = tid / DD, d = tid - c*DD;
        d_Wt[d*COUTC + c] = weight[tid];
    }

    // tid = n*NP + p : sum fmap over 64 channels at this pixel (coalesced along p)
    {
        int n = tid / NP, p = tid - n*NP;
        const float* base = fmap + (size_t)n * CINC * NP + p;
        float s = 0.f;
        #pragma unroll
        for (int c = 0; c < CINC; c++) s += base[c*NP];
        d_S[tid] = s;
    }
}

// K2: 3x3 box sum (zero-padded) -> quantized bin -> scatter-min first occurrence
__global__ void k_bin() {
    int tid = blockIdx.x * blockDim.x + threadIdx.x;
    int n = tid / NP, p = tid - n*NP;
    int h = p / WW, w = p - h*WW;
    const float* S = d_S + n*NP;

    float sum = 0.f;
    #pragma unroll
    for (int dy = -1; dy <= 1; dy++) {
        int y = h + dy;
        if (y < 0 || y >= HH) continue;
        #pragma unroll
        for (int dx = -1; dx <= 1; dx++) {
            int x = w + dx;
            if (x < 0 || x >= WW) continue;
            sum += S[y*WW + x];
        }
    }
    float mean = sum / (float)DD;          // patches.mean(axis=2) incl. padded zeros
    int s = (int)(mean * 100.0f);          // trunc toward zero == astype(int32)
    int b = s + 512;                       // - MIN_SUMMARY
    b = b < 0 ? 0 : (b > MEM-1 ? MEM-1 : b);
    d_bins[tid] = b;
    atomicMin(&d_first[n*MEM + b], p);     // first-occurring patch index per bin
}

// K3: one block per (bin, image); only populated bins do work (~35/image).
// 64 threads: stage the 576-elem representative patch in shared, each thread
// computes one output channel as dot(patch, Wt[:,c]) + bias[c].
__global__ void __launch_bounds__(64) k_rep(const float* __restrict__ fmap,
                                            const float* __restrict__ bias) {
    int b = blockIdx.x, n = blockIdx.y;
    int p = d_first[n*MEM + b];
    if (p >= NP) return;                   // unused bin

    __shared__ float sh[DD];
    int t = threadIdx.x;
    int h = p / WW, w = p - (p / WW) * WW;

    for (int d = t; d < DD; d += 64) {
        int cin = d / 9, r = d - cin*9;
        int kh = r / 3, kw = r - kh*3;
        int y = h + kh - 1, x = w + kw - 1;
        float v = 0.f;
        if (y >= 0 && y < HH && x >= 0 && x < WW)
            v = fmap[(((size_t)n*CINC + cin)*HH + y)*WW + x];
        sh[d] = v;
    }
    __syncthreads();

    float acc = bias[t];
    #pragma unroll 8
    for (int d = 0; d < DD; d++)
        acc = fmaf(sh[d], d_Wt[d*COUTC + t], acc);   // coalesced Wt across warp

    d_rep[((size_t)n*MEM + b)*COUTC + t] = acc;
}

// K4: out[(n*64+c)*NP + p] = rep[n][bins[n][p]][c]  (coalesced writes)
__global__ void k_out(float* __restrict__ out) {
    int tid = blockIdx.x * blockDim.x + threadIdx.x;
    int p  = tid % NP;
    int nc = tid / NP;
    int c  = nc % COUTC;
    int n  = nc / COUTC;
    int b  = d_bins[n*NP + p];
    out[tid] = d_rep[((size_t)n*MEM + b)*COUTC + c];
}

extern "C" void kernel_launch(void* const* d_in, const int* in_sizes, int n_in,
                              void* d_out, int out_size) {
    const float* fmap   = (const float*)d_in[0];
    const float* weight = (const float*)d_in[1];
    const float* bias   = (const float*)d_in[2];
    float* out = (float*)d_out;

    (void)in_sizes; (void)n_in; (void)out_size;

    // 100352 threads covers channel-sum work and (as subsets) first-init + transpose
    k_prep<<<(NIMG*NP)/256, 256>>>(fmap, weight);
    k_bin<<<(NIMG*NP)/256, 256>>>();
    dim3 repGrid(MEM, NIMG);
    k_rep<<<repGrid, 64>>>(fmap, bias);
    k_out<<<(NIMG*COUTC*NP)/256, 256>>>(out);
}